// round 9
// baseline (speedup 1.0000x reference)
#include <cuda_runtime.h>
#include <cuda_fp16.h>
#include <math.h>
#include <stdint.h>

#define NNODES 16384
#define HID 64
#define NEDGES 524288
#define UNITS 256
#define ASCALE 16384.0f
#define ASCALE_INV 6.103515625e-05f

// scratch
__device__ __half g_ah[(size_t)NNODES * NNODES];   // A as fp16*16384 (written by L1 adj)
__device__ __half g_bt[HID * NNODES];              // XW fp16 transposed [64][N]
__device__ float  g_h[NNODES * HID];               // layer-1 h fp32
__device__ __half g_h16[NNODES * HID];             // layer-2 h fp16
__device__ float  g_part[2 * NNODES * HID];        // split-K partials
__device__ __half g_wdt[UNITS * 2 * HID];          // Wd^T fp16 [256][128]

// ===========================================================================
// helpers
// ===========================================================================
__device__ __forceinline__ uint32_t smem_u32(const void* p) {
    uint32_t a;
    asm("{ .reg .u64 t; cvta.to.shared.u64 t, %1; cvt.u32.u64 %0, t; }"
        : "=r"(a) : "l"(p));
    return a;
}
__device__ __forceinline__ void cp_async16(uint32_t dst, const void* src) {
    asm volatile("cp.async.cg.shared.global [%0], [%1], 16;" :: "r"(dst), "l"(src));
}
__device__ __forceinline__ void cp_commit() {
    asm volatile("cp.async.commit_group;" ::: "memory");
}
__device__ __forceinline__ void ldsm_x4(uint32_t* r, uint32_t addr) {
    asm volatile("ldmatrix.sync.aligned.m8n8.x4.shared.b16 {%0,%1,%2,%3}, [%4];"
                 : "=r"(r[0]), "=r"(r[1]), "=r"(r[2]), "=r"(r[3]) : "r"(addr));
}
__device__ __forceinline__ void mma16(float* d, const uint32_t* a, uint32_t b0, uint32_t b1) {
    asm volatile(
        "mma.sync.aligned.m16n8k16.row.col.f32.f16.f16.f32 "
        "{%0,%1,%2,%3}, {%4,%5,%6,%7}, {%8,%9}, {%0,%1,%2,%3};"
        : "+f"(d[0]), "+f"(d[1]), "+f"(d[2]), "+f"(d[3])
        : "r"(a[0]), "r"(a[1]), "r"(a[2]), "r"(a[3]), "r"(b0), "r"(b1));
}

// ===========================================================================
// transpose + fp32->fp16: in [RIN][CIN] f32 -> out [CIN][RIN] half (Wd only)
// ===========================================================================
template <int RIN, int CIN>
__global__ void transpose_h(const float* __restrict__ in, __half* __restrict__ out) {
    __shared__ float t[32][33];
    const int bx = blockIdx.x, by = blockIdx.y;
    const int x = threadIdx.x, y = threadIdx.y;   // 32 x 8
#pragma unroll
    for (int i = 0; i < 32; i += 8)
        t[y + i][x] = in[(size_t)(bx * 32 + y + i) * CIN + by * 32 + x];
    __syncthreads();
#pragma unroll
    for (int i = 0; i < 32; i += 8)
        out[(size_t)(by * 32 + y + i) * RIN + bx * 32 + x] = __float2half(t[x][y + i]);
}

// ===========================================================================
// adj_mma_l1: layer-1 adjacency GEMM, fused fp32->fp16 conversion.
// part[y][M,64] = (A*ASCALE fp16)[M, khalf] @ Bt[64, khalf]^T ; also writes
// the converted fp16 A tile to Ah (grid covers A exactly once).
// A path: LDG fp32 -> regs -> cvt -> swizzled fp16 smem (+ STG to Ah).
// B path: cp.async triple buffer. BM=128, BN=64, BK=64, 8 warps (4x2).
// ===========================================================================
#define KSPLIT 2
#define KHALF (NNODES / KSPLIT)
#define L1_NIT (KHALF / 64)             // 128
#define L1_ABUF 16384                   // 128 rows * 128B, swizzled
#define L1_BST 144
#define L1_BBUF (64 * L1_BST)           // 9216
#define L1_OFF_B (2 * L1_ABUF)          // A double buffer first
#define SMEM_L1 (2 * L1_ABUF + 3 * L1_BBUF)   // 60416

__global__ __launch_bounds__(256, 2)
void adj_mma_l1(const float* __restrict__ A, const __half* __restrict__ Bt,
                float* __restrict__ part, __half* __restrict__ Ah) {
    extern __shared__ char dsm[];
    const uint32_t sbase = smem_u32(dsm);
    const int tid = threadIdx.x;
    const int lane = tid & 31, wid = tid >> 5;
    const int wm = wid >> 1, wn = wid & 1;
    const int gr = lane >> 2, tg = lane & 3;
    const int m0 = blockIdx.x * 128;
    const int kbase = blockIdx.y * KHALF;
    float* P = part + (size_t)blockIdx.y * NNODES * HID;

    // conversion ownership: row rmy, 32-half column window
    const int rmy = tid >> 1;
    const int chalf = (tid & 1) * 32;
    const int gb = (tid & 1) * 4;           // first granule of my window
    const int rsw_my = rmy & 7;

    // ldsm lane geometry
    const int rowA0 = wm * 32 + (lane & 15);      // + mf*16
    const uint32_t boff = (uint32_t)(((lane & 7) + ((lane >> 4) & 1) * 8) * L1_BST
                                     + ((lane >> 3) & 1) * 16);
    const int ghalf = lane >> 4;                  // 0/1: k-granule select

    float acc[2][4][4];
#pragma unroll
    for (int mf = 0; mf < 2; mf++)
#pragma unroll
        for (int nf = 0; nf < 4; nf++)
#pragma unroll
            for (int q = 0; q < 4; q++) acc[mf][nf][q] = 0.0f;

    float4 v[8];
    auto ldg_a = [&](int kt) {
        const float* src = A + (size_t)(m0 + rmy) * NNODES + kbase + kt * 64 + chalf;
#pragma unroll
        for (int i = 0; i < 8; i++) v[i] = *(const float4*)(src + i * 4);
    };
    auto load_b = [&](int stage, int kt) {
        uint32_t sb = sbase + L1_OFF_B + stage * L1_BBUF;
        const int k0 = kbase + kt * 64;
#pragma unroll
        for (int i = 0; i < 2; i++) {
            int g = tid + i * 256;
            int r = g >> 3, c = g & 7;
            cp_async16(sb + r * L1_BST + c * 16,
                       Bt + (size_t)r * NNODES + k0 + c * 8);
        }
        cp_commit();
    };

    ldg_a(0);
    load_b(0, 0);
    load_b(1, 1);

    for (int it = 0; it < L1_NIT; ++it) {
        // convert my 32 floats -> 16 half2 -> swizzled smem + global Ah
        const uint32_t abuf = sbase + (it & 1) * L1_ABUF;
        uint32_t hh[16];
#pragma unroll
        for (int i = 0; i < 8; i++) {
            __half2 p0 = __floats2half2_rn(v[i].x * ASCALE, v[i].y * ASCALE);
            __half2 p1 = __floats2half2_rn(v[i].z * ASCALE, v[i].w * ASCALE);
            hh[2 * i]     = *reinterpret_cast<uint32_t*>(&p0);
            hh[2 * i + 1] = *reinterpret_cast<uint32_t*>(&p1);
        }
        __half* gdst = Ah + (size_t)(m0 + rmy) * NNODES + kbase + it * 64 + chalf;
#pragma unroll
        for (int j = 0; j < 4; j++) {
            uint4 val = make_uint4(hh[4 * j], hh[4 * j + 1], hh[4 * j + 2], hh[4 * j + 3]);
            int g = gb + j;
            *(uint4*)(dsm + (it & 1) * L1_ABUF + rmy * 128 + ((g ^ rsw_my) << 4)) = val;
            *(uint4*)(gdst + 8 * j) = val;
        }

        asm volatile("cp.async.wait_group 1;" ::: "memory");
        __syncthreads();

        if (it + 1 < L1_NIT) ldg_a(it + 1);
        if (it + 2 < L1_NIT) load_b((it + 2) % 3, it + 2);
        else cp_commit();

        const uint32_t sb = sbase + L1_OFF_B + (it % 3) * L1_BBUF;
#pragma unroll
        for (int ks = 0; ks < 4; ++ks) {
            uint32_t a[2][4], bq[2][4];
            const int g = 2 * ks + ghalf;
#pragma unroll
            for (int mf = 0; mf < 2; mf++) {
                const int row = rowA0 + mf * 16;
                ldsm_x4(a[mf], abuf + row * 128 + ((g ^ (row & 7)) << 4));
            }
#pragma unroll
            for (int p = 0; p < 2; p++)
                ldsm_x4(bq[p], sb + (wn * 32 + p * 16) * L1_BST + ks * 32 + boff);
#pragma unroll
            for (int mf = 0; mf < 2; mf++)
#pragma unroll
                for (int p = 0; p < 2; p++) {
                    mma16(acc[mf][2 * p + 0], a[mf], bq[p][0], bq[p][1]);
                    mma16(acc[mf][2 * p + 1], a[mf], bq[p][2], bq[p][3]);
                }
        }
    }

    // epilogue: raw (scaled) partials
#pragma unroll
    for (int mf = 0; mf < 2; mf++) {
#pragma unroll
        for (int nf = 0; nf < 4; nf++) {
            const int row = m0 + wm * 32 + mf * 16 + gr;
            const int col = wn * 32 + nf * 8 + 2 * tg;
            *(float2*)&P[(size_t)row * 64 + col] =
                make_float2(acc[mf][nf][0], acc[mf][nf][1]);
            *(float2*)&P[(size_t)(row + 8) * 64 + col] =
                make_float2(acc[mf][nf][2], acc[mf][nf][3]);
        }
    }
}

// ===========================================================================
// adj_mma_h: layer-2 adjacency GEMM on prebuilt fp16 A (unchanged from R7)
// ===========================================================================
#define NIT (KHALF / 64)
#define ADJ_AST 144
#define ADJ_BST 144
#define ADJ_STAGE (128 * ADJ_AST + 64 * ADJ_BST)
#define SMEM_ADJ (3 * ADJ_STAGE)

__global__ __launch_bounds__(256, 2)
void adj_mma_h(const __half* __restrict__ A, const __half* __restrict__ Bt,
               float* __restrict__ part) {
    extern __shared__ char dsm[];
    const uint32_t sbase = smem_u32(dsm);
    const int tid = threadIdx.x;
    const int lane = tid & 31, wid = tid >> 5;
    const int wm = wid >> 1, wn = wid & 1;
    const int gr = lane >> 2, tg = lane & 3;
    const int m0 = blockIdx.x * 128;
    const int kbase = blockIdx.y * KHALF;
    float* P = part + (size_t)blockIdx.y * NNODES * HID;

    const uint32_t aoff = (uint32_t)(((lane & 7) + ((lane >> 3) & 1) * 8) * ADJ_AST
                                     + ((lane >> 4) & 1) * 16);
    const uint32_t boff = (uint32_t)(((lane & 7) + ((lane >> 4) & 1) * 8) * ADJ_BST
                                     + ((lane >> 3) & 1) * 16);

    float acc[2][4][4];
#pragma unroll
    for (int mf = 0; mf < 2; mf++)
#pragma unroll
        for (int nf = 0; nf < 4; nf++)
#pragma unroll
            for (int q = 0; q < 4; q++) acc[mf][nf][q] = 0.0f;

    auto load_tile = [&](int stage, int kt) {
        uint32_t sa = sbase + stage * ADJ_STAGE;
        uint32_t sb = sa + 128 * ADJ_AST;
        const int k0 = kbase + kt * 64;
#pragma unroll
        for (int i = 0; i < 4; i++) {
            int g = tid + i * 256;
            int r = g >> 3, c = g & 7;
            cp_async16(sa + r * ADJ_AST + c * 16,
                       A + (size_t)(m0 + r) * NNODES + k0 + c * 8);
        }
#pragma unroll
        for (int i = 0; i < 2; i++) {
            int g = tid + i * 256;
            int r = g >> 3, c = g & 7;
            cp_async16(sb + r * ADJ_BST + c * 16,
                       Bt + (size_t)r * NNODES + k0 + c * 8);
        }
        cp_commit();
    };

    load_tile(0, 0);
    load_tile(1, 1);

    for (int it = 0; it < NIT; ++it) {
        const int s = it % 3;
        asm volatile("cp.async.wait_group 1;" ::: "memory");
        __syncthreads();
        if (it + 2 < NIT) load_tile((it + 2) % 3, it + 2);
        else cp_commit();

        const uint32_t sa = sbase + s * ADJ_STAGE;
        const uint32_t sb = sa + 128 * ADJ_AST;

#pragma unroll
        for (int ks = 0; ks < 4; ++ks) {
            uint32_t a[2][4], bq[2][4];
#pragma unroll
            for (int mf = 0; mf < 2; mf++)
                ldsm_x4(a[mf], sa + (wm * 32 + mf * 16) * ADJ_AST + ks * 32 + aoff);
#pragma unroll
            for (int p = 0; p < 2; p++)
                ldsm_x4(bq[p], sb + (wn * 32 + p * 16) * ADJ_BST + ks * 32 + boff);
#pragma unroll
            for (int mf = 0; mf < 2; mf++)
#pragma unroll
                for (int p = 0; p < 2; p++) {
                    mma16(acc[mf][2 * p + 0], a[mf], bq[p][0], bq[p][1]);
                    mma16(acc[mf][2 * p + 1], a[mf], bq[p][2], bq[p][3]);
                }
        }
    }

#pragma unroll
    for (int mf = 0; mf < 2; mf++) {
#pragma unroll
        for (int nf = 0; nf < 4; nf++) {
            const int row = m0 + wm * 32 + mf * 16 + gr;
            const int col = wn * 32 + nf * 8 + 2 * tg;
            *(float2*)&P[(size_t)row * 64 + col] =
                make_float2(acc[mf][nf][0], acc[mf][nf][1]);
            *(float2*)&P[(size_t)(row + 8) * 64 + col] =
                make_float2(acc[mf][nf][2], acc[mf][nf][3]);
        }
    }
}

// ===========================================================================
// reduce: C = sigmoid((p0+p1)*ASCALE_INV + bias); fp32 or fp16 output
// ===========================================================================
__global__ __launch_bounds__(256)
void reduce_sigmoid_f(const float* __restrict__ part, const float* __restrict__ bias,
                      float* __restrict__ C) {
    const int i = blockIdx.x * 256 + threadIdx.x;
    const float4 p0 = *(const float4*)&part[i * 4];
    const float4 p1 = *(const float4*)&part[NNODES * HID + i * 4];
    const float4 bb = *(const float4*)&bias[(i * 4) & 63];
    float4 o;
    o.x = 1.0f / (1.0f + expf(-((p0.x + p1.x) * ASCALE_INV + bb.x)));
    o.y = 1.0f / (1.0f + expf(-((p0.y + p1.y) * ASCALE_INV + bb.y)));
    o.z = 1.0f / (1.0f + expf(-((p0.z + p1.z) * ASCALE_INV + bb.z)));
    o.w = 1.0f / (1.0f + expf(-((p0.w + p1.w) * ASCALE_INV + bb.w)));
    *(float4*)&C[i * 4] = o;
}
__global__ __launch_bounds__(256)
void reduce_sigmoid_h(const float* __restrict__ part, const float* __restrict__ bias,
                      __half* __restrict__ C) {
    const int i = blockIdx.x * 256 + threadIdx.x;
    const float4 p0 = *(const float4*)&part[i * 4];
    const float4 p1 = *(const float4*)&part[NNODES * HID + i * 4];
    const float4 bb = *(const float4*)&bias[(i * 4) & 63];
    float ox = 1.0f / (1.0f + expf(-((p0.x + p1.x) * ASCALE_INV + bb.x)));
    float oy = 1.0f / (1.0f + expf(-((p0.y + p1.y) * ASCALE_INV + bb.y)));
    float oz = 1.0f / (1.0f + expf(-((p0.z + p1.z) * ASCALE_INV + bb.z)));
    float ow = 1.0f / (1.0f + expf(-((p0.w + p1.w) * ASCALE_INV + bb.w)));
    __half2 h0 = __floats2half2_rn(ox, oy);
    __half2 h1 = __floats2half2_rn(oz, ow);
    uint2 st;
    st.x = *reinterpret_cast<uint32_t*>(&h0);
    st.y = *reinterpret_cast<uint32_t*>(&h1);
    *(uint2*)&C[i * 4] = st;
}

// ===========================================================================
// edge_mma_h: fused relu(concat(h[s],h[d]) @ Wd + bd) @ Wo -> softmax * mask
// (unchanged from R7)
// ===========================================================================
#define E_WST 272
#define E_EST 80
#define OFF_WD 0
#define OFF_ES0 (256 * E_WST)
#define OFF_ES1 (OFF_ES0 + 128 * E_EST)
#define OFF_RED (OFF_ES1 + 128 * E_EST)
#define SMEM_EDGE (OFF_RED + 4096)

__global__ __launch_bounds__(512, 1)
void edge_mma_h(const __half* __restrict__ h, const int* __restrict__ edges,
                const int* __restrict__ mask, const __half* __restrict__ WdT,
                const float* __restrict__ bd, const float* __restrict__ Wo,
                const float* __restrict__ bo, float* __restrict__ out) {
    extern __shared__ char dsm[];
    const uint32_t sbase = smem_u32(dsm);
    const int tid = threadIdx.x;
    const int lane = tid & 31, wid = tid >> 5;
    const int wm = wid >> 2, wn = wid & 3;
    const int gr = lane >> 2, tg = lane & 3;
    const int e0 = blockIdx.x * 128;

    const uint32_t aoff = (uint32_t)(((lane & 7) + ((lane >> 3) & 1) * 8) * E_EST
                                     + ((lane >> 4) & 1) * 16);
    const uint32_t boff = (uint32_t)(((lane & 7) + ((lane >> 4) & 1) * 8) * E_WST
                                     + ((lane >> 3) & 1) * 16);

    float acc[2][8][4];
#pragma unroll
    for (int mf = 0; mf < 2; mf++)
#pragma unroll
        for (int nf = 0; nf < 8; nf++)
#pragma unroll
            for (int q = 0; q < 4; q++) acc[mf][nf][q] = 0.0f;

#pragma unroll
    for (int i = 0; i < 8; i++) {
        int g = tid + i * 512;
        int r = g >> 4, c = g & 15;
        cp_async16(sbase + OFF_WD + r * E_WST + c * 16, WdT + (size_t)r * 128 + c * 8);
    }
    cp_commit();

    auto load_es = [&](int ch) {
        uint32_t es = sbase + ((ch & 1) ? OFF_ES1 : OFF_ES0);
        const int sel = ch >> 1, hc = (ch & 1) * 32;
        int e = tid >> 2, c = tid & 3;
        int node = __ldg(&edges[2 * (e0 + e) + sel]);
        cp_async16(es + e * E_EST + c * 16, h + (size_t)node * 64 + hc + c * 8);
        cp_commit();
    };

    load_es(0);
    for (int ch = 0; ch < 4; ++ch) {
        if (ch < 3) load_es(ch + 1);
        else cp_commit();
        asm volatile("cp.async.wait_group 1;" ::: "memory");
        __syncthreads();

        const uint32_t es = sbase + ((ch & 1) ? OFF_ES1 : OFF_ES0);
        const uint32_t wd = sbase + OFF_WD;
#pragma unroll
        for (int ks2 = 0; ks2 < 2; ++ks2) {
            uint32_t a[2][4], bq[4][4];
            const int kglob = ch * 2 + ks2;
#pragma unroll
            for (int mf = 0; mf < 2; mf++)
                ldsm_x4(a[mf], es + (wm * 32 + mf * 16) * E_EST + ks2 * 32 + aoff);
#pragma unroll
            for (int p = 0; p < 4; p++)
                ldsm_x4(bq[p], wd + (wn * 64 + p * 16) * E_WST + kglob * 32 + boff);
#pragma unroll
            for (int mf = 0; mf < 2; mf++)
#pragma unroll
                for (int p = 0; p < 4; p++) {
                    mma16(acc[mf][2 * p + 0], a[mf], bq[p][0], bq[p][1]);
                    mma16(acc[mf][2 * p + 1], a[mf], bq[p][2], bq[p][3]);
                }
        }
        __syncthreads();
    }

    float p[2][2][2];
#pragma unroll
    for (int mf = 0; mf < 2; mf++)
#pragma unroll
        for (int hh = 0; hh < 2; hh++) { p[mf][hh][0] = 0.f; p[mf][hh][1] = 0.f; }

#pragma unroll
    for (int nf = 0; nf < 8; nf++) {
        const int cb = wn * 64 + nf * 8 + 2 * tg;
        const float bd0 = bd[cb], bd1 = bd[cb + 1];
        const float w00 = Wo[2 * cb + 0], w01 = Wo[2 * cb + 1];
        const float w10 = Wo[2 * cb + 2], w11 = Wo[2 * cb + 3];
#pragma unroll
        for (int mf = 0; mf < 2; mf++) {
            float d0 = fmaxf(acc[mf][nf][0] + bd0, 0.f);
            float d1 = fmaxf(acc[mf][nf][1] + bd1, 0.f);
            float d2 = fmaxf(acc[mf][nf][2] + bd0, 0.f);
            float d3 = fmaxf(acc[mf][nf][3] + bd1, 0.f);
            p[mf][0][0] = fmaf(d0, w00, fmaf(d1, w10, p[mf][0][0]));
            p[mf][0][1] = fmaf(d0, w01, fmaf(d1, w11, p[mf][0][1]));
            p[mf][1][0] = fmaf(d2, w00, fmaf(d3, w10, p[mf][1][0]));
            p[mf][1][1] = fmaf(d2, w01, fmaf(d3, w11, p[mf][1][1]));
        }
    }
#pragma unroll
    for (int off = 1; off <= 2; off <<= 1)
#pragma unroll
        for (int mf = 0; mf < 2; mf++)
#pragma unroll
            for (int hh = 0; hh < 2; hh++) {
                p[mf][hh][0] += __shfl_xor_sync(0xffffffffu, p[mf][hh][0], off);
                p[mf][hh][1] += __shfl_xor_sync(0xffffffffu, p[mf][hh][1], off);
            }
    float* red = (float*)(dsm + OFF_RED);
    if (tg == 0) {
#pragma unroll
        for (int mf = 0; mf < 2; mf++)
#pragma unroll
            for (int hh = 0; hh < 2; hh++) {
                int r = wm * 32 + mf * 16 + hh * 8 + gr;
                red[(wn * 128 + r) * 2 + 0] = p[mf][hh][0];
                red[(wn * 128 + r) * 2 + 1] = p[mf][hh][1];
            }
    }
    __syncthreads();
    if (tid < 128) {
        float v0 = bo[0], v1 = bo[1];
#pragma unroll
        for (int w = 0; w < 4; w++) {
            v0 += red[(w * 128 + tid) * 2 + 0];
            v1 += red[(w * 128 + tid) * 2 + 1];
        }
        int e = e0 + tid;
        float m = fmaxf(v0, v1);
        float x0 = expf(v0 - m), x1 = expf(v1 - m);
        float inv = 1.0f / (x0 + x1);
        float mk = (float)mask[e];
        out[2 * e + 0] = x0 * inv * mk;
        out[2 * e + 1] = x1 * inv * mk;
    }
}

// ===========================================================================
// gemm_n64t (SIMT): bt[64][N](fp16) = (A[M,K] @ B[K,64])^T  (small K: 128/64)
// ===========================================================================
__global__ __launch_bounds__(256, 2)
void gemm_n64t(const float* __restrict__ A, const float* __restrict__ B,
               __half* __restrict__ bt, int K) {
    const int BM = 128, BK = 32;
    __shared__ float Asm[BK][BM + 4];
    __shared__ float Bsm[BK][64];
    __shared__ __half tile[64][136];    // transposed output staging

    const int tid = threadIdx.x;
    const int tcol = tid & 15;
    const int trow = tid >> 4;
    const int m0 = blockIdx.x * BM;

    float acc[8][4];
#pragma unroll
    for (int r = 0; r < 8; r++)
#pragma unroll
        for (int c = 0; c < 4; c++) acc[r][c] = 0.0f;

    const int lrow = tid >> 3;
    const int lk4 = tid & 7;
    const int brow = tid >> 4;
    const int bc4 = tid & 15;

    const int nchunk = K / BK;
    for (int ch = 0; ch < nchunk; ++ch) {
        const int k0 = ch * BK;
#pragma unroll
        for (int i = 0; i < 4; i++) {
            int r = lrow + 32 * i;
            float4 v = *(const float4*)&A[(size_t)(m0 + r) * K + k0 + lk4 * 4];
            Asm[lk4 * 4 + 0][r] = v.x;
            Asm[lk4 * 4 + 1][r] = v.y;
            Asm[lk4 * 4 + 2][r] = v.z;
            Asm[lk4 * 4 + 3][r] = v.w;
        }
#pragma unroll
        for (int i = 0; i < 2; i++) {
            int r = brow + 16 * i;
            *(float4*)&Bsm[r][bc4 * 4] = *(const float4*)&B[(size_t)(k0 + r) * 64 + bc4 * 4];
        }
        __syncthreads();
#pragma unroll
        for (int k = 0; k < BK; k++) {
            float4 a0 = *(const float4*)&Asm[k][trow * 8];
            float4 a1 = *(const float4*)&Asm[k][trow * 8 + 4];
            float4 b = *(const float4*)&Bsm[k][tcol * 4];
            float ar[8] = {a0.x, a0.y, a0.z, a0.w, a1.x, a1.y, a1.z, a1.w};
            float br[4] = {b.x, b.y, b.z, b.w};
#pragma unroll
            for (int r = 0; r < 8; r++)
#pragma unroll
                for (int c = 0; c < 4; c++) acc[r][c] = fmaf(ar[r], br[c], acc[r][c]);
        }
        __syncthreads();
    }

    // stage transposed fp16 tile: tile[col][row] over 64 x 128
#pragma unroll
    for (int c = 0; c < 4; c++) {
        __half2 h0 = __floats2half2_rn(acc[0][c], acc[1][c]);
        __half2 h1 = __floats2half2_rn(acc[2][c], acc[3][c]);
        __half2 h2 = __floats2half2_rn(acc[4][c], acc[5][c]);
        __half2 h3 = __floats2half2_rn(acc[6][c], acc[7][c]);
        uint4 val;
        val.x = *reinterpret_cast<uint32_t*>(&h0);
        val.y = *reinterpret_cast<uint32_t*>(&h1);
        val.z = *reinterpret_cast<uint32_t*>(&h2);
        val.w = *reinterpret_cast<uint32_t*>(&h3);
        *(uint4*)&tile[tcol * 4 + c][trow * 8] = val;
    }
    __syncthreads();
    // write out: row rr (0..63), 16 chunks of 8 halfs
    const int rr = tid >> 2;
#pragma unroll
    for (int j = 0; j < 4; j++) {
        int chk = (tid & 3) + 4 * j;
        uint4 val = *(uint4*)&tile[rr][chk * 8];
        *(uint4*)&bt[(size_t)rr * NNODES + m0 + chk * 8] = val;
    }
}

// ===========================================================================
extern "C" void kernel_launch(void* const* d_in, const int* in_sizes, int n_in,
                              void* d_out, int out_size) {
    const float* X     = (const float*)d_in[0];
    const float* Adj   = (const float*)d_in[1];
    const int*   edges = (const int*)d_in[2];
    const int*   smask = (const int*)d_in[3];
    const float* W1    = (const float*)d_in[4];
    const float* b1    = (const float*)d_in[5];
    const float* W2    = (const float*)d_in[6];
    const float* b2    = (const float*)d_in[7];
    const float* Wd    = (const float*)d_in[8];
    const float* bd    = (const float*)d_in[9];
    const float* Wo    = (const float*)d_in[10];
    const float* bo    = (const float*)d_in[11];
    float* out = (float*)d_out;

    __half *ah, *bt, *h16, *wdt;
    float *h, *part;
    cudaGetSymbolAddress((void**)&ah, g_ah);
    cudaGetSymbolAddress((void**)&bt, g_bt);
    cudaGetSymbolAddress((void**)&h16, g_h16);
    cudaGetSymbolAddress((void**)&wdt, g_wdt);
    cudaGetSymbolAddress((void**)&h, g_h);
    cudaGetSymbolAddress((void**)&part, g_part);

    cudaFuncSetAttribute(adj_mma_l1, cudaFuncAttributeMaxDynamicSharedMemorySize, SMEM_L1);
    cudaFuncSetAttribute(adj_mma_h, cudaFuncAttributeMaxDynamicSharedMemorySize, SMEM_ADJ);
    cudaFuncSetAttribute(edge_mma_h, cudaFuncAttributeMaxDynamicSharedMemorySize, SMEM_EDGE);

    dim3 tb(32, 8);
    dim3 agrid(NNODES / 128, KSPLIT);
    const int rgrid = (NNODES * HID / 4) / 256;

    transpose_h<2 * HID, UNITS><<<dim3(4, 8), tb>>>(Wd, wdt);

    // layer 1 (fused A conversion)
    gemm_n64t<<<NNODES / 128, 256>>>(X, W1, bt, 128);
    adj_mma_l1<<<agrid, 256, SMEM_L1>>>(Adj, bt, part, ah);
    reduce_sigmoid_f<<<rgrid, 256>>>(part, b1, h);
    // layer 2
    gemm_n64t<<<NNODES / 128, 256>>>(h, W2, bt, 64);
    adj_mma_h<<<agrid, 256, SMEM_ADJ>>>(ah, bt, part);
    reduce_sigmoid_h<<<rgrid, 256>>>(part, b2, h16);
    // fused edge MLP
    edge_mma_h<<<NEDGES / 128, 512, SMEM_EDGE>>>(h16, edges, smask, wdt, bd, Wo, bo, out);
}

// round 13
// speedup vs baseline: 1.1266x; 1.1266x over previous
#include <cuda_runtime.h>
#include <cuda_fp16.h>
#include <math.h>
#include <stdint.h>

#define NNODES 16384
#define HID 64
#define NEDGES 524288
#define UNITS 256
#define ASCALE 16384.0f
#define ASCALE_INV 6.103515625e-05f
#define KSPLIT 4
#define KQ (NNODES / KSPLIT)            // 4096

// scratch
__device__ __half g_ah[(size_t)NNODES * NNODES];   // A as fp16*16384 (512 MB)
__device__ __half g_bt[HID * NNODES];              // XW fp16 transposed [64][N]
__device__ float  g_h[NNODES * HID];               // layer-1 h fp32
__device__ __half g_h16[NNODES * HID];             // layer-2 h fp16
__device__ float  g_part[KSPLIT * NNODES * HID];   // split-K partials (16 MB)
__device__ __half g_wdt[UNITS * 2 * HID];          // Wd^T fp16 [256][128]

// ===========================================================================
// helpers
// ===========================================================================
__device__ __forceinline__ uint32_t smem_u32(const void* p) {
    uint32_t a;
    asm("{ .reg .u64 t; cvta.to.shared.u64 t, %1; cvt.u32.u64 %0, t; }"
        : "=r"(a) : "l"(p));
    return a;
}
__device__ __forceinline__ void cp_async16(uint32_t dst, const void* src) {
    asm volatile("cp.async.cg.shared.global [%0], [%1], 16;" :: "r"(dst), "l"(src));
}
__device__ __forceinline__ void cp_commit() {
    asm volatile("cp.async.commit_group;" ::: "memory");
}
__device__ __forceinline__ void ldsm_x4(uint32_t* r, uint32_t addr) {
    asm volatile("ldmatrix.sync.aligned.m8n8.x4.shared.b16 {%0,%1,%2,%3}, [%4];"
                 : "=r"(r[0]), "=r"(r[1]), "=r"(r[2]), "=r"(r[3]) : "r"(addr));
}
__device__ __forceinline__ void mma16(float* d, const uint32_t* a, uint32_t b0, uint32_t b1) {
    asm volatile(
        "mma.sync.aligned.m16n8k16.row.col.f32.f16.f16.f32 "
        "{%0,%1,%2,%3}, {%4,%5,%6,%7}, {%8,%9}, {%0,%1,%2,%3};"
        : "+f"(d[0]), "+f"(d[1]), "+f"(d[2]), "+f"(d[3])
        : "r"(a[0]), "r"(a[1]), "r"(a[2]), "r"(a[3]), "r"(b0), "r"(b1));
}

// ===========================================================================
// convert_a: Ah = fp16(A * 16384)  (streaming, 1 GiB read + 0.5 GiB write)
// ===========================================================================
__global__ __launch_bounds__(256)
void convert_a(const float* __restrict__ A, __half* __restrict__ Ah) {
    const size_t nunits = (size_t)NNODES * NNODES / 8;
    const size_t stride = (size_t)gridDim.x * 256;
    for (size_t u = (size_t)blockIdx.x * 256 + threadIdx.x; u < nunits; u += stride) {
        float4 v0 = *(const float4*)(A + u * 8);
        float4 v1 = *(const float4*)(A + u * 8 + 4);
        __half2 h0 = __floats2half2_rn(v0.x * ASCALE, v0.y * ASCALE);
        __half2 h1 = __floats2half2_rn(v0.z * ASCALE, v0.w * ASCALE);
        __half2 h2 = __floats2half2_rn(v1.x * ASCALE, v1.y * ASCALE);
        __half2 h3 = __floats2half2_rn(v1.z * ASCALE, v1.w * ASCALE);
        uint4 o;
        o.x = *reinterpret_cast<uint32_t*>(&h0);
        o.y = *reinterpret_cast<uint32_t*>(&h1);
        o.z = *reinterpret_cast<uint32_t*>(&h2);
        o.w = *reinterpret_cast<uint32_t*>(&h3);
        *(uint4*)(Ah + u * 8) = o;
    }
}

// ===========================================================================
// transpose + fp32->fp16 (Wd only, tiny)
// ===========================================================================
template <int RIN, int CIN>
__global__ void transpose_h(const float* __restrict__ in, __half* __restrict__ out) {
    __shared__ float t[32][33];
    const int bx = blockIdx.x, by = blockIdx.y;
    const int x = threadIdx.x, y = threadIdx.y;   // 32 x 8
#pragma unroll
    for (int i = 0; i < 32; i += 8)
        t[y + i][x] = in[(size_t)(bx * 32 + y + i) * CIN + by * 32 + x];
    __syncthreads();
#pragma unroll
    for (int i = 0; i < 32; i += 8)
        out[(size_t)(by * 32 + y + i) * RIN + bx * 32 + x] = __float2half(t[x][y + i]);
}

// ===========================================================================
// adj_mma_h: part[y][M,64] = Ah[M, Kq] @ Bt[64, Kq]^T (fp16 m16n8k16)
// BM=128, BN=64, BK=64, 8 warps (4x2), 3-stage cp.async, 2 CTAs/SM.
// Grid (128, KSPLIT=4) = 512 CTAs for fine-grained load balance.
// ===========================================================================
#define NIT (KQ / 64)                   // 64
#define ADJ_AST 144
#define ADJ_BST 144
#define ADJ_STAGE (128 * ADJ_AST + 64 * ADJ_BST)
#define SMEM_ADJ (3 * ADJ_STAGE)

__global__ __launch_bounds__(256, 2)
void adj_mma_h(const __half* __restrict__ A, const __half* __restrict__ Bt,
               float* __restrict__ part) {
    extern __shared__ char dsm[];
    const uint32_t sbase = smem_u32(dsm);
    const int tid = threadIdx.x;
    const int lane = tid & 31, wid = tid >> 5;
    const int wm = wid >> 1, wn = wid & 1;
    const int gr = lane >> 2, tg = lane & 3;
    const int m0 = blockIdx.x * 128;
    const int kbase = blockIdx.y * KQ;
    float* P = part + (size_t)blockIdx.y * NNODES * HID;

    const uint32_t aoff = (uint32_t)(((lane & 7) + ((lane >> 3) & 1) * 8) * ADJ_AST
                                     + ((lane >> 4) & 1) * 16);
    const uint32_t boff = (uint32_t)(((lane & 7) + ((lane >> 4) & 1) * 8) * ADJ_BST
                                     + ((lane >> 3) & 1) * 16);

    float acc[2][4][4];
#pragma unroll
    for (int mf = 0; mf < 2; mf++)
#pragma unroll
        for (int nf = 0; nf < 4; nf++)
#pragma unroll
            for (int q = 0; q < 4; q++) acc[mf][nf][q] = 0.0f;

    auto load_tile = [&](int stage, int kt) {
        uint32_t sa = sbase + stage * ADJ_STAGE;
        uint32_t sb = sa + 128 * ADJ_AST;
        const int k0 = kbase + kt * 64;
#pragma unroll
        for (int i = 0; i < 4; i++) {
            int g = tid + i * 256;
            int r = g >> 3, c = g & 7;
            cp_async16(sa + r * ADJ_AST + c * 16,
                       A + (size_t)(m0 + r) * NNODES + k0 + c * 8);
        }
#pragma unroll
        for (int i = 0; i < 2; i++) {
            int g = tid + i * 256;
            int r = g >> 3, c = g & 7;
            cp_async16(sb + r * ADJ_BST + c * 16,
                       Bt + (size_t)r * NNODES + k0 + c * 8);
        }
        cp_commit();
    };

    load_tile(0, 0);
    load_tile(1, 1);

    for (int it = 0; it < NIT; ++it) {
        const int s = it % 3;
        asm volatile("cp.async.wait_group 1;" ::: "memory");
        __syncthreads();
        if (it + 2 < NIT) load_tile((it + 2) % 3, it + 2);
        else cp_commit();

        const uint32_t sa = sbase + s * ADJ_STAGE;
        const uint32_t sb = sa + 128 * ADJ_AST;

#pragma unroll
        for (int ks = 0; ks < 4; ++ks) {
            uint32_t a[2][4], bq[2][4];
#pragma unroll
            for (int mf = 0; mf < 2; mf++)
                ldsm_x4(a[mf], sa + (wm * 32 + mf * 16) * ADJ_AST + ks * 32 + aoff);
#pragma unroll
            for (int p = 0; p < 2; p++)
                ldsm_x4(bq[p], sb + (wn * 32 + p * 16) * ADJ_BST + ks * 32 + boff);
#pragma unroll
            for (int mf = 0; mf < 2; mf++)
#pragma unroll
                for (int p = 0; p < 2; p++) {
                    mma16(acc[mf][2 * p + 0], a[mf], bq[p][0], bq[p][1]);
                    mma16(acc[mf][2 * p + 1], a[mf], bq[p][2], bq[p][3]);
                }
        }
    }

#pragma unroll
    for (int mf = 0; mf < 2; mf++) {
#pragma unroll
        for (int nf = 0; nf < 4; nf++) {
            const int row = m0 + wm * 32 + mf * 16 + gr;
            const int col = wn * 32 + nf * 8 + 2 * tg;
            *(float2*)&P[(size_t)row * 64 + col] =
                make_float2(acc[mf][nf][0], acc[mf][nf][1]);
            *(float2*)&P[(size_t)(row + 8) * 64 + col] =
                make_float2(acc[mf][nf][2], acc[mf][nf][3]);
        }
    }
}

// ===========================================================================
// reduce: C = sigmoid((p0+p1+p2+p3)*ASCALE_INV + bias); fp32 or fp16 output
// ===========================================================================
__global__ __launch_bounds__(256)
void reduce_sigmoid_f(const float* __restrict__ part, const float* __restrict__ bias,
                      float* __restrict__ C) {
    const int i = blockIdx.x * 256 + threadIdx.x;
    float4 s = *(const float4*)&part[i * 4];
#pragma unroll
    for (int y = 1; y < KSPLIT; y++) {
        const float4 p = *(const float4*)&part[(size_t)y * NNODES * HID + i * 4];
        s.x += p.x; s.y += p.y; s.z += p.z; s.w += p.w;
    }
    const float4 bb = *(const float4*)&bias[(i * 4) & 63];
    float4 o;
    o.x = 1.0f / (1.0f + expf(-(s.x * ASCALE_INV + bb.x)));
    o.y = 1.0f / (1.0f + expf(-(s.y * ASCALE_INV + bb.y)));
    o.z = 1.0f / (1.0f + expf(-(s.z * ASCALE_INV + bb.z)));
    o.w = 1.0f / (1.0f + expf(-(s.w * ASCALE_INV + bb.w)));
    *(float4*)&C[i * 4] = o;
}
__global__ __launch_bounds__(256)
void reduce_sigmoid_h(const float* __restrict__ part, const float* __restrict__ bias,
                      __half* __restrict__ C) {
    const int i = blockIdx.x * 256 + threadIdx.x;
    float4 s = *(const float4*)&part[i * 4];
#pragma unroll
    for (int y = 1; y < KSPLIT; y++) {
        const float4 p = *(const float4*)&part[(size_t)y * NNODES * HID + i * 4];
        s.x += p.x; s.y += p.y; s.z += p.z; s.w += p.w;
    }
    const float4 bb = *(const float4*)&bias[(i * 4) & 63];
    float ox = 1.0f / (1.0f + expf(-(s.x * ASCALE_INV + bb.x)));
    float oy = 1.0f / (1.0f + expf(-(s.y * ASCALE_INV + bb.y)));
    float oz = 1.0f / (1.0f + expf(-(s.z * ASCALE_INV + bb.z)));
    float ow = 1.0f / (1.0f + expf(-(s.w * ASCALE_INV + bb.w)));
    __half2 h0 = __floats2half2_rn(ox, oy);
    __half2 h1 = __floats2half2_rn(oz, ow);
    uint2 st;
    st.x = *reinterpret_cast<uint32_t*>(&h0);
    st.y = *reinterpret_cast<uint32_t*>(&h1);
    *(uint2*)&C[i * 4] = st;
}

// ===========================================================================
// edge_mma_h: fused relu(concat(h[s],h[d]) @ Wd + bd) @ Wo -> softmax * mask
// ===========================================================================
#define E_WST 272
#define E_EST 80
#define OFF_WD 0
#define OFF_ES0 (256 * E_WST)
#define OFF_ES1 (OFF_ES0 + 128 * E_EST)
#define OFF_RED (OFF_ES1 + 128 * E_EST)
#define SMEM_EDGE (OFF_RED + 4096)

__global__ __launch_bounds__(512, 1)
void edge_mma_h(const __half* __restrict__ h, const int* __restrict__ edges,
                const int* __restrict__ mask, const __half* __restrict__ WdT,
                const float* __restrict__ bd, const float* __restrict__ Wo,
                const float* __restrict__ bo, float* __restrict__ out) {
    extern __shared__ char dsm[];
    const uint32_t sbase = smem_u32(dsm);
    const int tid = threadIdx.x;
    const int lane = tid & 31, wid = tid >> 5;
    const int wm = wid >> 2, wn = wid & 3;
    const int gr = lane >> 2, tg = lane & 3;
    const int e0 = blockIdx.x * 128;

    const uint32_t aoff = (uint32_t)(((lane & 7) + ((lane >> 3) & 1) * 8) * E_EST
                                     + ((lane >> 4) & 1) * 16);
    const uint32_t boff = (uint32_t)(((lane & 7) + ((lane >> 4) & 1) * 8) * E_WST
                                     + ((lane >> 3) & 1) * 16);

    float acc[2][8][4];
#pragma unroll
    for (int mf = 0; mf < 2; mf++)
#pragma unroll
        for (int nf = 0; nf < 8; nf++)
#pragma unroll
            for (int q = 0; q < 4; q++) acc[mf][nf][q] = 0.0f;

#pragma unroll
    for (int i = 0; i < 8; i++) {
        int g = tid + i * 512;
        int r = g >> 4, c = g & 15;
        cp_async16(sbase + OFF_WD + r * E_WST + c * 16, WdT + (size_t)r * 128 + c * 8);
    }
    cp_commit();

    auto load_es = [&](int ch) {
        uint32_t es = sbase + ((ch & 1) ? OFF_ES1 : OFF_ES0);
        const int sel = ch >> 1, hc = (ch & 1) * 32;
        int e = tid >> 2, c = tid & 3;
        int node = __ldg(&edges[2 * (e0 + e) + sel]);
        cp_async16(es + e * E_EST + c * 16, h + (size_t)node * 64 + hc + c * 8);
        cp_commit();
    };

    load_es(0);
    for (int ch = 0; ch < 4; ++ch) {
        if (ch < 3) load_es(ch + 1);
        else cp_commit();
        asm volatile("cp.async.wait_group 1;" ::: "memory");
        __syncthreads();

        const uint32_t es = sbase + ((ch & 1) ? OFF_ES1 : OFF_ES0);
        const uint32_t wd = sbase + OFF_WD;
#pragma unroll
        for (int ks2 = 0; ks2 < 2; ++ks2) {
            uint32_t a[2][4], bq[4][4];
            const int kglob = ch * 2 + ks2;
#pragma unroll
            for (int mf = 0; mf < 2; mf++)
                ldsm_x4(a[mf], es + (wm * 32 + mf * 16) * E_EST + ks2 * 32 + aoff);
#pragma unroll
            for (int p = 0; p < 4; p++)
                ldsm_x4(bq[p], wd + (wn * 64 + p * 16) * E_WST + kglob * 32 + boff);
#pragma unroll
            for (int mf = 0; mf < 2; mf++)
#pragma unroll
                for (int p = 0; p < 4; p++) {
                    mma16(acc[mf][2 * p + 0], a[mf], bq[p][0], bq[p][1]);
                    mma16(acc[mf][2 * p + 1], a[mf], bq[p][2], bq[p][3]);
                }
        }
        __syncthreads();
    }

    float p[2][2][2];
#pragma unroll
    for (int mf = 0; mf < 2; mf++)
#pragma unroll
        for (int hh = 0; hh < 2; hh++) { p[mf][hh][0] = 0.f; p[mf][hh][1] = 0.f; }

#pragma unroll
    for (int nf = 0; nf < 8; nf++) {
        const int cb = wn * 64 + nf * 8 + 2 * tg;
        const float bd0 = bd[cb], bd1 = bd[cb + 1];
        const float w00 = Wo[2 * cb + 0], w01 = Wo[2 * cb + 1];
        const float w10 = Wo[2 * cb + 2], w11 = Wo[2 * cb + 3];
#pragma unroll
        for (int mf = 0; mf < 2; mf++) {
            float d0 = fmaxf(acc[mf][nf][0] + bd0, 0.f);
            float d1 = fmaxf(acc[mf][nf][1] + bd1, 0.f);
            float d2 = fmaxf(acc[mf][nf][2] + bd0, 0.f);
            float d3 = fmaxf(acc[mf][nf][3] + bd1, 0.f);
            p[mf][0][0] = fmaf(d0, w00, fmaf(d1, w10, p[mf][0][0]));
            p[mf][0][1] = fmaf(d0, w01, fmaf(d1, w11, p[mf][0][1]));
            p[mf][1][0] = fmaf(d2, w00, fmaf(d3, w10, p[mf][1][0]));
            p[mf][1][1] = fmaf(d2, w01, fmaf(d3, w11, p[mf][1][1]));
        }
    }
#pragma unroll
    for (int off = 1; off <= 2; off <<= 1)
#pragma unroll
        for (int mf = 0; mf < 2; mf++)
#pragma unroll
            for (int hh = 0; hh < 2; hh++) {
                p[mf][hh][0] += __shfl_xor_sync(0xffffffffu, p[mf][hh][0], off);
                p[mf][hh][1] += __shfl_xor_sync(0xffffffffu, p[mf][hh][1], off);
            }
    float* red = (float*)(dsm + OFF_RED);
    if (tg == 0) {
#pragma unroll
        for (int mf = 0; mf < 2; mf++)
#pragma unroll
            for (int hh = 0; hh < 2; hh++) {
                int r = wm * 32 + mf * 16 + hh * 8 + gr;
                red[(wn * 128 + r) * 2 + 0] = p[mf][hh][0];
                red[(wn * 128 + r) * 2 + 1] = p[mf][hh][1];
            }
    }
    __syncthreads();
    if (tid < 128) {
        float v0 = bo[0], v1 = bo[1];
#pragma unroll
        for (int w = 0; w < 4; w++) {
            v0 += red[(w * 128 + tid) * 2 + 0];
            v1 += red[(w * 128 + tid) * 2 + 1];
        }
        int e = e0 + tid;
        float m = fmaxf(v0, v1);
        float x0 = expf(v0 - m), x1 = expf(v1 - m);
        float inv = 1.0f / (x0 + x1);
        float mk = (float)mask[e];
        out[2 * e + 0] = x0 * inv * mk;
        out[2 * e + 1] = x1 * inv * mk;
    }
}

// ===========================================================================
// gemm_n64t (SIMT): bt[64][N](fp16) = (A[M,K] @ B[K,64])^T  (small K: 128/64)
// ===========================================================================
__global__ __launch_bounds__(256, 2)
void gemm_n64t(const float* __restrict__ A, const float* __restrict__ B,
               __half* __restrict__ bt, int K) {
    const int BM = 128, BK = 32;
    __shared__ float Asm[BK][BM + 4];
    __shared__ float Bsm[BK][64];
    __shared__ __half tile[64][136];

    const int tid = threadIdx.x;
    const int tcol = tid & 15;
    const int trow = tid >> 4;
    const int m0 = blockIdx.x * BM;

    float acc[8][4];
#pragma unroll
    for (int r = 0; r < 8; r++)
#pragma unroll
        for (int c = 0; c < 4; c++) acc[r][c] = 0.0f;

    const int lrow = tid >> 3;
    const int lk4 = tid & 7;
    const int brow = tid >> 4;
    const int bc4 = tid & 15;

    const int nchunk = K / BK;
    for (int ch = 0; ch < nchunk; ++ch) {
        const int k0 = ch * BK;
#pragma unroll
        for (int i = 0; i < 4; i++) {
            int r = lrow + 32 * i;
            float4 v = *(const float4*)&A[(size_t)(m0 + r) * K + k0 + lk4 * 4];
            Asm[lk4 * 4 + 0][r] = v.x;
            Asm[lk4 * 4 + 1][r] = v.y;
            Asm[lk4 * 4 + 2][r] = v.z;
            Asm[lk4 * 4 + 3][r] = v.w;
        }
#pragma unroll
        for (int i = 0; i < 2; i++) {
            int r = brow + 16 * i;
            *(float4*)&Bsm[r][bc4 * 4] = *(const float4*)&B[(size_t)(k0 + r) * 64 + bc4 * 4];
        }
        __syncthreads();
#pragma unroll
        for (int k = 0; k < BK; k++) {
            float4 a0 = *(const float4*)&Asm[k][trow * 8];
            float4 a1 = *(const float4*)&Asm[k][trow * 8 + 4];
            float4 b = *(const float4*)&Bsm[k][tcol * 4];
            float ar[8] = {a0.x, a0.y, a0.z, a0.w, a1.x, a1.y, a1.z, a1.w};
            float br[4] = {b.x, b.y, b.z, b.w};
#pragma unroll
            for (int r = 0; r < 8; r++)
#pragma unroll
                for (int c = 0; c < 4; c++) acc[r][c] = fmaf(ar[r], br[c], acc[r][c]);
        }
        __syncthreads();
    }

#pragma unroll
    for (int c = 0; c < 4; c++) {
        __half2 h0 = __floats2half2_rn(acc[0][c], acc[1][c]);
        __half2 h1 = __floats2half2_rn(acc[2][c], acc[3][c]);
        __half2 h2 = __floats2half2_rn(acc[4][c], acc[5][c]);
        __half2 h3 = __floats2half2_rn(acc[6][c], acc[7][c]);
        uint4 val;
        val.x = *reinterpret_cast<uint32_t*>(&h0);
        val.y = *reinterpret_cast<uint32_t*>(&h1);
        val.z = *reinterpret_cast<uint32_t*>(&h2);
        val.w = *reinterpret_cast<uint32_t*>(&h3);
        *(uint4*)&tile[tcol * 4 + c][trow * 8] = val;
    }
    __syncthreads();
    const int rr = tid >> 2;
#pragma unroll
    for (int j = 0; j < 4; j++) {
        int chk = (tid & 3) + 4 * j;
        uint4 val = *(uint4*)&tile[rr][chk * 8];
        *(uint4*)&bt[(size_t)rr * NNODES + m0 + chk * 8] = val;
    }
}

// ===========================================================================
extern "C" void kernel_launch(void* const* d_in, const int* in_sizes, int n_in,
                              void* d_out, int out_size) {
    const float* X     = (const float*)d_in[0];
    const float* Adj   = (const float*)d_in[1];
    const int*   edges = (const int*)d_in[2];
    const int*   smask = (const int*)d_in[3];
    const float* W1    = (const float*)d_in[4];
    const float* b1    = (const float*)d_in[5];
    const float* W2    = (const float*)d_in[6];
    const float* b2    = (const float*)d_in[7];
    const float* Wd    = (const float*)d_in[8];
    const float* bd    = (const float*)d_in[9];
    const float* Wo    = (const float*)d_in[10];
    const float* bo    = (const float*)d_in[11];
    float* out = (float*)d_out;

    __half *ah, *bt, *h16, *wdt;
    float *h, *part;
    cudaGetSymbolAddress((void**)&ah, g_ah);
    cudaGetSymbolAddress((void**)&bt, g_bt);
    cudaGetSymbolAddress((void**)&h16, g_h16);
    cudaGetSymbolAddress((void**)&wdt, g_wdt);
    cudaGetSymbolAddress((void**)&h, g_h);
    cudaGetSymbolAddress((void**)&part, g_part);

    cudaFuncSetAttribute(adj_mma_h, cudaFuncAttributeMaxDynamicSharedMemorySize, SMEM_ADJ);
    cudaFuncSetAttribute(edge_mma_h, cudaFuncAttributeMaxDynamicSharedMemorySize, SMEM_EDGE);

    dim3 tb(32, 8);
    dim3 agrid(NNODES / 128, KSPLIT);
    const int rgrid = (NNODES * HID / 4) / 256;

    convert_a<<<8192, 256>>>(Adj, ah);
    transpose_h<2 * HID, UNITS><<<dim3(4, 8), tb>>>(Wd, wdt);

    // layer 1
    gemm_n64t<<<NNODES / 128, 256>>>(X, W1, bt, 128);
    adj_mma_h<<<agrid, 256, SMEM_ADJ>>>(ah, bt, part);
    reduce_sigmoid_f<<<rgrid, 256>>>(part, b1, h);
    // layer 2
    gemm_n64t<<<NNODES / 128, 256>>>(h, W2, bt, 64);
    adj_mma_h<<<agrid, 256, SMEM_ADJ>>>(ah, bt, part);
    reduce_sigmoid_h<<<rgrid, 256>>>(part, b2, h16);
    // fused edge MLP
    edge_mma_h<<<NEDGES / 128, 512, SMEM_EDGE>>>(h16, edges, smask, wdt, bd, Wo, bo, out);
}